// round 6
// baseline (speedup 1.0000x reference)
#include <cuda_runtime.h>
#include <math.h>

#define DD     64
#define OO     32
#define KMIX   15
#define HIDN   60
#define FPITCH 68
#define SPITCH 36
#define UPITCH 68
#define LOG2PI 1.8378770664093453f
#define BMAX   8192

// ---------------- scratch ----------------
__device__ float scr_w  [(size_t)BMAX*16];     // mixture weights
__device__ float scr_f  [(size_t)BMAX*4096];   // F row-major

__device__ __forceinline__ float4 ld4(const float* p){ return *reinterpret_cast<const float4*>(p); }
__device__ __forceinline__ void   st4(float* p, float4 v){ *reinterpret_cast<float4*>(p) = v; }
__device__ __forceinline__ float4 fma4(float a, float4 b, float4 c){
    c.x = fmaf(a,b.x,c.x); c.y = fmaf(a,b.y,c.y);
    c.z = fmaf(a,b.z,c.z); c.w = fmaf(a,b.w,c.w);
    return c;
}
__device__ __forceinline__ float dot4acc(float4 a, float4 b, float c){
    c = fmaf(a.x,b.x,c); c = fmaf(a.y,b.y,c);
    c = fmaf(a.z,b.z,c); c = fmaf(a.w,b.w,c);
    return c;
}

// ========== K00: MLP + softmax -> scr_w (warp per batch) ==========
__global__ __launch_bounds__(256)
void rkn_weights(const float* __restrict__ g_mean,
                 const float* __restrict__ g_w1,
                 const float* __restrict__ g_b1,
                 const float* __restrict__ g_w2,
                 const float* __restrict__ g_b2)
{
    __shared__ float sw1[HIDN*65];
    __shared__ float sw2[KMIX*HIDN];
    __shared__ float sb1[HIDN];
    __shared__ float sb2[KMIX];
    __shared__ float smn[8][64];
    __shared__ float shd[8][64];

    const int tid = threadIdx.x;
    for (int i=tid;i<HIDN*DD;i+=256){ int u=i>>6, d=i&63; sw1[u*65+d]=g_w1[i]; }
    for (int i=tid;i<KMIX*HIDN;i+=256) sw2[i]=g_w2[i];
    if (tid<HIDN) sb1[tid]=g_b1[tid];
    if (tid<KMIX) sb2[tid]=g_b2[tid];

    const int w = tid>>5, lane = tid&31;
    const int b = blockIdx.x*8 + w;
    smn[w][lane]    = g_mean[b*DD + lane];
    smn[w][lane+32] = g_mean[b*DD + 32 + lane];
    __syncthreads();

    {
        float acc = sb1[lane];
        #pragma unroll 16
        for (int d=0;d<DD;d++) acc = fmaf(sw1[lane*65+d], smn[w][d], acc);
        shd[w][lane] = acc > 0.f ? acc : expm1f(acc);
        int u = lane + 32;
        if (u < HIDN) {
            float a2 = sb1[u];
            #pragma unroll 16
            for (int d=0;d<DD;d++) a2 = fmaf(sw1[u*65+d], smn[w][d], a2);
            shd[w][u] = a2 > 0.f ? a2 : expm1f(a2);
        }
    }
    __syncwarp();

    if (lane < 16) {
        float acc = -1e30f;
        if (lane < KMIX) {
            acc = sb2[lane];
            #pragma unroll 15
            for (int j=0;j<HIDN;j++) acc = fmaf(sw2[lane*HIDN+j], shd[w][j], acc);
        }
        float mx = acc;
        #pragma unroll
        for (int off=8;off;off>>=1) mx = fmaxf(mx, __shfl_xor_sync(0xFFFFu, mx, off));
        float e = expf(acc - mx);
        float s = e;
        #pragma unroll
        for (int off=8;off;off>>=1) s += __shfl_xor_sync(0xFFFFu, s, off);
        if (lane < KMIX) scr_w[(size_t)b*16 + lane] = e / s;
    }
}

// ========== K0: F_all = W @ basis ==========
__global__ __launch_bounds__(256)
void rkn_mixf(const float* __restrict__ g_basis)
{
    __shared__ float sW[16][16];
    const int tid = threadIdx.x;
    const int b0 = blockIdx.x*16;
    if (tid < 240) sW[tid/15][tid%15] = scr_w[(size_t)(b0 + tid/15)*16 + (tid%15)];
    __syncthreads();

    const int n = blockIdx.y*1024 + tid*4;
    float4 bs[KMIX];
    #pragma unroll
    for (int k=0;k<KMIX;k++) bs[k] = ld4(g_basis + k*4096 + n);

    #pragma unroll 4
    for (int bb=0;bb<16;bb++){
        float4 acc = make_float4(0.f,0.f,0.f,0.f);
        #pragma unroll
        for (int k=0;k<KMIX;k++) acc = fma4(sW[bb][k], bs[k], acc);
        st4(scr_f + (size_t)(b0+bb)*4096 + n, acc);
    }
}

// ========== Fused predict + update (256 threads, 4 CTAs/SM) ==========
// smem: sP 64x64 | sFt 64x68 (union: HP/U 32x68, S+recip after) | sT 64x64 | misc
#define F_OFF_P    0
#define F_OFF_FT   (F_OFF_P  + DD*DD)          // 4096
#define F_OFF_T    (F_OFF_FT + DD*FPITCH)      // 8448
#define F_OFF_M    (F_OFF_T  + DD*DD)          // 12544
#define F_OFF_PM   (F_OFF_M  + DD)
#define F_OFF_INN  (F_OFF_PM + DD)
#define F_OFF_RED  (F_OFF_INN+ OO)
#define F_FLOATS   (F_OFF_RED+ 4)
// unions inside sFt region (F dead after GEMM2)
#define F_OFF_U    F_OFF_FT                    // U/HP: 32 rows pitch 68 = 2176
#define F_OFF_S    (F_OFF_FT + 2176)           // S: 32x36 = 1152 -> ends 3328 < 4352
#define F_OFF_RCP  (F_OFF_FT + 3328)           // 32

__global__ __launch_bounds__(256, 4)
void rkn_fused(const float* __restrict__ g_mean,
               const float* __restrict__ g_cov,
               const float* __restrict__ g_obs,
               const float* __restrict__ g_pnf,
               const float* __restrict__ g_pnd,
               const float* __restrict__ g_onf,
               const float* __restrict__ g_ond,
               const float* __restrict__ g_Hw,
               const float* __restrict__ g_Hb,
               float* __restrict__ o_mean,
               float* __restrict__ o_cov,
               float* __restrict__ o_ll)
{
    extern __shared__ float smem[];
    float* sP   = smem + F_OFF_P;
    float* sFt  = smem + F_OFF_FT;
    float* sT   = smem + F_OFF_T;
    float* sU   = smem + F_OFF_U;    // HP, then U (solve in place)
    float* sS   = smem + F_OFF_S;
    float* sRcp = smem + F_OFF_RCP;
    float* sm_  = smem + F_OFF_M;
    float* spm  = smem + F_OFF_PM;
    float* sinn = smem + F_OFF_INN;
    float* sred = smem + F_OFF_RED;

    const int b   = blockIdx.x;
    const int tid = threadIdx.x;
    const int tx  = tid & 15;
    const int ty  = tid >> 4;

    // ---------------- loads ----------------
    if (tid < DD) sm_[tid] = g_mean[b*DD + tid];
    {   // P
        const float* Pg = g_cov + (size_t)b*DD*DD;
        int base = tid*16;
        #pragma unroll
        for (int q=0;q<4;q++) st4(sP + base + q*4, ld4(Pg + base + q*4));
    }
    {   // F: coalesced load, scatter-transpose
        const float* Fg = scr_f + (size_t)b*4096;
        int base = tid*16;
        int i = base >> 6;
        #pragma unroll
        for (int q=0;q<4;q++){
            int g = base + q*4;
            float4 v = ld4(Fg + g);
            int j = g & 63;
            sFt[(j+0)*FPITCH + i] = v.x;
            sFt[(j+1)*FPITCH + i] = v.y;
            sFt[(j+2)*FPITCH + i] = v.z;
            sFt[(j+3)*FPITCH + i] = v.w;
        }
    }
    __syncthreads();

    // pred_mean = F @ m
    if (tid < DD) {
        float acc = 0.f;
        #pragma unroll 16
        for (int k=0;k<DD;k++) acc = fmaf(sFt[k*FPITCH + tid], sm_[k], acc);
        spm[tid] = acc;
    }

    // GEMM1: T = F @ P
    {
        const int r0 = ty*4, c0 = tx*4;
        float4 acc0=make_float4(0,0,0,0), acc1=acc0, acc2=acc0, acc3=acc0;
        for (int k=0;k<DD;k+=4){
            float4 a0 = ld4(sFt + (k+0)*FPITCH + r0);
            float4 a1 = ld4(sFt + (k+1)*FPITCH + r0);
            float4 a2 = ld4(sFt + (k+2)*FPITCH + r0);
            float4 a3 = ld4(sFt + (k+3)*FPITCH + r0);
            float4 p0 = ld4(sP + (k+0)*DD + c0);
            acc0=fma4(a0.x,p0,acc0); acc1=fma4(a0.y,p0,acc1); acc2=fma4(a0.z,p0,acc2); acc3=fma4(a0.w,p0,acc3);
            float4 p1 = ld4(sP + (k+1)*DD + c0);
            acc0=fma4(a1.x,p1,acc0); acc1=fma4(a1.y,p1,acc1); acc2=fma4(a1.z,p1,acc2); acc3=fma4(a1.w,p1,acc3);
            float4 p2 = ld4(sP + (k+2)*DD + c0);
            acc0=fma4(a2.x,p2,acc0); acc1=fma4(a2.y,p2,acc1); acc2=fma4(a2.z,p2,acc2); acc3=fma4(a2.w,p2,acc3);
            float4 p3 = ld4(sP + (k+3)*DD + c0);
            acc0=fma4(a3.x,p3,acc0); acc1=fma4(a3.y,p3,acc1); acc2=fma4(a3.z,p3,acc2); acc3=fma4(a3.w,p3,acc3);
        }
        st4(sT + (r0+0)*DD + c0, acc0);
        st4(sT + (r0+1)*DD + c0, acc1);
        st4(sT + (r0+2)*DD + c0, acc2);
        st4(sT + (r0+3)*DD + c0, acc3);
    }
    __syncthreads();

    // innovation -> sinn
    if (tid < OO) {
        float acc = g_Hb[tid];
        const float* hwr = g_Hw + tid*DD;
        #pragma unroll 8
        for (int k=0;k<DD;k++) acc = fmaf(hwr[k], spm[k], acc);
        sinn[tid] = g_obs[b*OO + tid] - acc;
    }

    // GEMM2: pred_cov = T @ F^T + Q -> sP (in place)
    {
        const int r0 = ty*4, c0 = tx*4;
        float4 acc0=make_float4(0,0,0,0), acc1=acc0, acc2=acc0, acc3=acc0;
        for (int k=0;k<DD;k+=4){
            float4 t0 = ld4(sT + (r0+0)*DD + k);
            float4 t1 = ld4(sT + (r0+1)*DD + k);
            float4 t2 = ld4(sT + (r0+2)*DD + k);
            float4 t3 = ld4(sT + (r0+3)*DD + k);
            float4 f0 = ld4(sFt + (k+0)*FPITCH + c0);
            acc0=fma4(t0.x,f0,acc0); acc1=fma4(t1.x,f0,acc1); acc2=fma4(t2.x,f0,acc2); acc3=fma4(t3.x,f0,acc3);
            float4 f1 = ld4(sFt + (k+1)*FPITCH + c0);
            acc0=fma4(t0.y,f1,acc0); acc1=fma4(t1.y,f1,acc1); acc2=fma4(t2.y,f1,acc2); acc3=fma4(t3.y,f1,acc3);
            float4 f2 = ld4(sFt + (k+2)*FPITCH + c0);
            acc0=fma4(t0.z,f2,acc0); acc1=fma4(t1.z,f2,acc1); acc2=fma4(t2.z,f2,acc2); acc3=fma4(t3.z,f2,acc3);
            float4 f3 = ld4(sFt + (k+3)*FPITCH + c0);
            acc0=fma4(t0.w,f3,acc0); acc1=fma4(t1.w,f3,acc1); acc2=fma4(t2.w,f3,acc2); acc3=fma4(t3.w,f3,acc3);
        }
        float pa[4][3], pb[4][3];
        #pragma unroll
        for (int i=0;i<4;i++)
            #pragma unroll
            for (int r=0;r<3;r++){
                pa[i][r] = g_pnf[(r0+i)*3 + r];
                pb[i][r] = g_pnf[(c0+i)*3 + r];
            }
        float* accp[4] = { &acc0.x, &acc1.x, &acc2.x, &acc3.x };
        #pragma unroll
        for (int i=0;i<4;i++){
            #pragma unroll
            for (int j=0;j<4;j++){
                float q = pa[i][0]*pb[j][0];
                q = fmaf(pa[i][1], pb[j][1], q);
                q = fmaf(pa[i][2], pb[j][2], q);
                accp[i][j] += q;
            }
        }
        if (r0 == c0){
            #pragma unroll
            for (int i=0;i<4;i++) accp[i][i] += expf(g_pnd[r0+i]);
        }
        st4(sP + (r0+0)*DD + c0, acc0);
        st4(sP + (r0+1)*DD + c0, acc1);
        st4(sP + (r0+2)*DD + c0, acc2);
        st4(sP + (r0+3)*DD + c0, acc3);
    }
    __syncthreads();

    // HP = Hw @ pred_cov -> sU (pitch 68), F now dead
    {
        const int o0 = ty*2, c0 = tx*4;
        float4 accA = make_float4(0,0,0,0), accB = accA;
        const float* hw0 = g_Hw + (o0+0)*DD;
        const float* hw1 = g_Hw + (o0+1)*DD;
        for (int k=0;k<DD;k+=4){
            float4 h0 = ld4(hw0 + k);
            float4 h1 = ld4(hw1 + k);
            float4 p0 = ld4(sP + (k+0)*DD + c0);
            accA=fma4(h0.x,p0,accA); accB=fma4(h1.x,p0,accB);
            float4 p1 = ld4(sP + (k+1)*DD + c0);
            accA=fma4(h0.y,p1,accA); accB=fma4(h1.y,p1,accB);
            float4 p2 = ld4(sP + (k+2)*DD + c0);
            accA=fma4(h0.z,p2,accA); accB=fma4(h1.z,p2,accB);
            float4 p3 = ld4(sP + (k+3)*DD + c0);
            accA=fma4(h0.w,p3,accA); accB=fma4(h1.w,p3,accB);
        }
        st4(sU + (o0+0)*UPITCH + c0, accA);
        st4(sU + (o0+1)*UPITCH + c0, accB);
    }
    __syncthreads();

    // S = HP @ Hw^T + Rn ; also stage innovation into U col 64
    if (tid < OO) sU[tid*UPITCH + 64] = sinn[tid];
    {
        const int o0 = ty*2, p0 = tx*2;
        float a00=0.f,a01=0.f,a10=0.f,a11=0.f;
        const float* hw0 = g_Hw + (p0+0)*DD;
        const float* hw1 = g_Hw + (p0+1)*DD;
        for (int k=0;k<DD;k+=4){
            float4 x0 = ld4(sU + (o0+0)*UPITCH + k);
            float4 x1 = ld4(sU + (o0+1)*UPITCH + k);
            float4 y0 = ld4(hw0 + k);
            float4 y1 = ld4(hw1 + k);
            a00 = dot4acc(x0,y0,a00); a01 = dot4acc(x0,y1,a01);
            a10 = dot4acc(x1,y0,a10); a11 = dot4acc(x1,y1,a11);
        }
        float oa[2][3], ob[2][3];
        #pragma unroll
        for (int i=0;i<2;i++)
            #pragma unroll
            for (int r=0;r<3;r++){
                oa[i][r] = g_onf[(o0+i)*3 + r];
                ob[i][r] = g_onf[(p0+i)*3 + r];
            }
        a00 += oa[0][0]*ob[0][0] + oa[0][1]*ob[0][1] + oa[0][2]*ob[0][2];
        a01 += oa[0][0]*ob[1][0] + oa[0][1]*ob[1][1] + oa[0][2]*ob[1][2];
        a10 += oa[1][0]*ob[0][0] + oa[1][1]*ob[0][1] + oa[1][2]*ob[0][2];
        a11 += oa[1][0]*ob[1][0] + oa[1][1]*ob[1][1] + oa[1][2]*ob[1][2];
        if (o0 == p0){
            a00 += expf(g_ond[o0+0]);
            a11 += expf(g_ond[o0+1]);
        }
        sS[(o0+0)*SPITCH + p0+0] = a00;
        sS[(o0+0)*SPITCH + p0+1] = a01;
        sS[(o0+1)*SPITCH + p0+0] = a10;
        sS[(o0+1)*SPITCH + p0+1] = a11;
    }
    __syncthreads();

    // Cholesky (warp 0) + logdet + recip
    if (tid < 32) {
        const int i = tid;
        for (int j=0;j<32;j++){
            float s = 0.f;
            if (i >= j){
                s = sS[i*SPITCH + j];
                for (int k=0;k<j;k++) s = fmaf(-sS[i*SPITCH+k], sS[j*SPITCH+k], s);
            }
            float dj  = __shfl_sync(0xffffffffu, s, j);
            float ljj = sqrtf(dj);
            if (i == j)      sS[i*SPITCH+j] = ljj;
            else if (i > j)  sS[i*SPITCH+j] = s / ljj;
            __syncwarp();
        }
        float di = sS[i*SPITCH+i];
        sRcp[i] = 1.0f / di;
        float ld = logf(di);
        #pragma unroll
        for (int off=16;off;off>>=1) ld += __shfl_xor_sync(0xffffffffu, ld, off);
        if (i == 0) sred[0] = 2.f*ld;
    }
    __syncthreads();

    // forward solve L*[U|v] in place: columns thread-private
    if (tid < 65) {
        const int c = tid;
        for (int r=0;r<OO;r++){
            float val = sU[r*UPITCH + c];
            for (int k=0;k<r;k++) val = fmaf(-sS[r*SPITCH+k], sU[k*UPITCH + c], val);
            sU[r*UPITCH + c] = val * sRcp[r];
        }
    }
    __syncthreads();

    // outputs
    if (tid == 64) {
        float quad = 0.f;
        #pragma unroll
        for (int o=0;o<OO;o++){ float v = sU[o*UPITCH + 64]; quad = fmaf(v, v, quad); }
        o_ll[b] = -0.5f*(sred[0] + quad + 32.f*LOG2PI);
    }
    if (tid < DD) {   // post_mean = pm + U^T v
        float acc = spm[tid];
        #pragma unroll 8
        for (int o=0;o<OO;o++) acc = fmaf(sU[o*UPITCH + tid], sU[o*UPITCH + 64], acc);
        o_mean[(size_t)b*DD + tid] = acc;
    }

    // post_cov = pred_cov - U^T U  (4x4 tile per thread)
    {
        const int r0 = ty*4, c0 = tx*4;
        float4 acc0=make_float4(0,0,0,0), acc1=acc0, acc2=acc0, acc3=acc0;
        #pragma unroll 4
        for (int o=0;o<OO;o++){
            float4 bv = ld4(sU + o*UPITCH + c0);
            float4 a  = ld4(sU + o*UPITCH + r0);
            acc0 = fma4(a.x, bv, acc0);
            acc1 = fma4(a.y, bv, acc1);
            acc2 = fma4(a.z, bv, acc2);
            acc3 = fma4(a.w, bv, acc3);
        }
        float* outr = o_cov + (size_t)b*4096;
        float4 accs[4] = {acc0, acc1, acc2, acc3};
        #pragma unroll
        for (int i=0;i<4;i++){
            float4 pc = ld4(sP + (r0+i)*DD + c0);
            st4(outr + (r0+i)*DD + c0,
                make_float4(pc.x - accs[i].x, pc.y - accs[i].y,
                            pc.z - accs[i].z, pc.w - accs[i].w));
        }
    }
}

extern "C" void kernel_launch(void* const* d_in, const int* in_sizes, int n_in,
                              void* d_out, int out_size)
{
    const float* g_mean  = (const float*)d_in[0];
    const float* g_cov   = (const float*)d_in[1];
    const float* g_obs   = (const float*)d_in[2];
    const float* g_w1    = (const float*)d_in[3];
    const float* g_b1    = (const float*)d_in[4];
    const float* g_w2    = (const float*)d_in[5];
    const float* g_b2    = (const float*)d_in[6];
    const float* g_basis = (const float*)d_in[7];
    const float* g_pnf   = (const float*)d_in[8];
    const float* g_pnd   = (const float*)d_in[9];
    const float* g_onf   = (const float*)d_in[10];
    const float* g_ond   = (const float*)d_in[11];
    const float* g_Hw    = (const float*)d_in[12];
    const float* g_Hb    = (const float*)d_in[13];

    int B = in_sizes[0] / DD;
    if (B > BMAX) B = BMAX;
    float* out    = (float*)d_out;
    float* o_mean = out;
    float* o_cov  = out + (size_t)B*DD;
    float* o_ll   = out + (size_t)B*DD + (size_t)B*DD*DD;

    const int f_smem = F_FLOATS * (int)sizeof(float);
    cudaFuncSetAttribute(rkn_fused, cudaFuncAttributeMaxDynamicSharedMemorySize, f_smem);

    rkn_weights<<<B/8, 256>>>(g_mean, g_w1, g_b1, g_w2, g_b2);
    rkn_mixf<<<dim3(B/16, 4), 256>>>(g_basis);
    rkn_fused<<<B, 256, f_smem>>>(g_mean, g_cov, g_obs, g_pnf, g_pnd, g_onf, g_ond,
                                  g_Hw, g_Hb, o_mean, o_cov, o_ll);
}

// round 7
// speedup vs baseline: 1.0685x; 1.0685x over previous
#include <cuda_runtime.h>
#include <math.h>

#define DD     64
#define OO     32
#define KMIX   15
#define HIDN   60
#define FPITCH 68
#define SPITCH 36
#define UPITCH 68
#define LOG2PI 1.8378770664093453f
#define BMAX   8192

// ---------------- scratch ----------------
__device__ float scr_cov[(size_t)BMAX*4096];   // pred_cov
__device__ float scr_hp [(size_t)BMAX*2176];   // HP rows pitch 68 (cols 0..63 valid)
__device__ float scr_s  [(size_t)BMAX*1024];   // S 32x32
__device__ float scr_pm [(size_t)BMAX*64];     // pred_mean
__device__ float scr_w  [(size_t)BMAX*16];     // mixture weights
__device__ float scr_f  [(size_t)BMAX*4096];   // F row-major

__device__ __forceinline__ float4 ld4(const float* p){ return *reinterpret_cast<const float4*>(p); }
__device__ __forceinline__ void   st4(float* p, float4 v){ *reinterpret_cast<float4*>(p) = v; }
__device__ __forceinline__ float4 fma4(float a, float4 b, float4 c){
    c.x = fmaf(a,b.x,c.x); c.y = fmaf(a,b.y,c.y);
    c.z = fmaf(a,b.z,c.z); c.w = fmaf(a,b.w,c.w);
    return c;
}
__device__ __forceinline__ float dot4acc(float4 a, float4 b, float c){
    c = fmaf(a.x,b.x,c); c = fmaf(a.y,b.y,c);
    c = fmaf(a.z,b.z,c); c = fmaf(a.w,b.w,c);
    return c;
}

// ========== K00: MLP + softmax -> scr_w (warp per batch) ==========
__global__ __launch_bounds__(256)
void rkn_weights(const float* __restrict__ g_mean,
                 const float* __restrict__ g_w1,
                 const float* __restrict__ g_b1,
                 const float* __restrict__ g_w2,
                 const float* __restrict__ g_b2)
{
    __shared__ float sw1[HIDN*65];
    __shared__ float sw2[KMIX*HIDN];
    __shared__ float sb1[HIDN];
    __shared__ float sb2[KMIX];
    __shared__ float smn[8][64];
    __shared__ float shd[8][64];

    const int tid = threadIdx.x;
    for (int i=tid;i<HIDN*DD;i+=256){ int u=i>>6, d=i&63; sw1[u*65+d]=g_w1[i]; }
    for (int i=tid;i<KMIX*HIDN;i+=256) sw2[i]=g_w2[i];
    if (tid<HIDN) sb1[tid]=g_b1[tid];
    if (tid<KMIX) sb2[tid]=g_b2[tid];

    const int w = tid>>5, lane = tid&31;
    const int b = blockIdx.x*8 + w;
    smn[w][lane]    = g_mean[b*DD + lane];
    smn[w][lane+32] = g_mean[b*DD + 32 + lane];
    __syncthreads();

    {
        float acc = sb1[lane];
        #pragma unroll 16
        for (int d=0;d<DD;d++) acc = fmaf(sw1[lane*65+d], smn[w][d], acc);
        shd[w][lane] = acc > 0.f ? acc : expm1f(acc);
        int u = lane + 32;
        if (u < HIDN) {
            float a2 = sb1[u];
            #pragma unroll 16
            for (int d=0;d<DD;d++) a2 = fmaf(sw1[u*65+d], smn[w][d], a2);
            shd[w][u] = a2 > 0.f ? a2 : expm1f(a2);
        }
    }
    __syncwarp();

    if (lane < 16) {
        float acc = -1e30f;
        if (lane < KMIX) {
            acc = sb2[lane];
            #pragma unroll 15
            for (int j=0;j<HIDN;j++) acc = fmaf(sw2[lane*HIDN+j], shd[w][j], acc);
        }
        float mx = acc;
        #pragma unroll
        for (int off=8;off;off>>=1) mx = fmaxf(mx, __shfl_xor_sync(0xFFFFu, mx, off));
        float e = expf(acc - mx);
        float s = e;
        #pragma unroll
        for (int off=8;off;off>>=1) s += __shfl_xor_sync(0xFFFFu, s, off);
        if (lane < KMIX) scr_w[(size_t)b*16 + lane] = e / s;
    }
}

// ========== K0: F_all = W @ basis ==========
__global__ __launch_bounds__(256)
void rkn_mixf(const float* __restrict__ g_basis)
{
    __shared__ float sW[16][16];
    const int tid = threadIdx.x;
    const int b0 = blockIdx.x*16;
    if (tid < 240) sW[tid/15][tid%15] = scr_w[(size_t)(b0 + tid/15)*16 + (tid%15)];
    __syncthreads();

    const int n = blockIdx.y*1024 + tid*4;
    float4 bs[KMIX];
    #pragma unroll
    for (int k=0;k<KMIX;k++) bs[k] = ld4(g_basis + k*4096 + n);

    #pragma unroll 4
    for (int bb=0;bb<16;bb++){
        float4 acc = make_float4(0.f,0.f,0.f,0.f);
        #pragma unroll
        for (int k=0;k<KMIX;k++) acc = fma4(sW[bb][k], bs[k], acc);
        st4(scr_f + (size_t)(b0+bb)*4096 + n, acc);
    }
}

// ========== K1: predict GEMMs (256 threads, 4 CTAs/SM) — unchanged from R5 ==========
#define K1_OFF_P   0
#define K1_OFF_FT  (K1_OFF_P  + DD*DD)
#define K1_OFF_T   (K1_OFF_FT + DD*FPITCH)
#define K1_OFF_M   (K1_OFF_T  + DD*DD)
#define K1_OFF_PM  (K1_OFF_M  + DD)
#define K1_FLOATS  (K1_OFF_PM + DD)
#define K1_OFF_HP  K1_OFF_FT

__global__ __launch_bounds__(256, 4)
void rkn_predict(const float* __restrict__ g_mean,
                 const float* __restrict__ g_cov,
                 const float* __restrict__ g_pnf,
                 const float* __restrict__ g_pnd,
                 const float* __restrict__ g_onf,
                 const float* __restrict__ g_ond,
                 const float* __restrict__ g_Hw)
{
    extern __shared__ float smem[];
    float* sP  = smem + K1_OFF_P;
    float* sFt = smem + K1_OFF_FT;
    float* sT  = smem + K1_OFF_T;
    float* sHP = smem + K1_OFF_HP;
    float* sm_ = smem + K1_OFF_M;
    float* spm = smem + K1_OFF_PM;

    const int b   = blockIdx.x;
    const int tid = threadIdx.x;
    const int tx  = tid & 15;
    const int ty  = tid >> 4;

    if (tid < DD) sm_[tid] = g_mean[b*DD + tid];
    {
        const float* Pg = g_cov + (size_t)b*DD*DD;
        int base = tid*16;
        #pragma unroll
        for (int q=0;q<4;q++) st4(sP + base + q*4, ld4(Pg + base + q*4));
    }
    {
        const float* Fg = scr_f + (size_t)b*4096;
        int base = tid*16;
        int i = base >> 6;
        #pragma unroll
        for (int q=0;q<4;q++){
            int g = base + q*4;
            float4 v = ld4(Fg + g);
            int j = g & 63;
            sFt[(j+0)*FPITCH + i] = v.x;
            sFt[(j+1)*FPITCH + i] = v.y;
            sFt[(j+2)*FPITCH + i] = v.z;
            sFt[(j+3)*FPITCH + i] = v.w;
        }
    }
    __syncthreads();

    if (tid < DD) {
        float acc = 0.f;
        #pragma unroll 16
        for (int k=0;k<DD;k++) acc = fmaf(sFt[k*FPITCH + tid], sm_[k], acc);
        spm[tid] = acc;
        scr_pm[(size_t)b*DD + tid] = acc;
    }

    // GEMM1: T = F @ P
    {
        const int r0 = ty*4, c0 = tx*4;
        float4 acc0=make_float4(0,0,0,0), acc1=acc0, acc2=acc0, acc3=acc0;
        for (int k=0;k<DD;k+=4){
            float4 a0 = ld4(sFt + (k+0)*FPITCH + r0);
            float4 a1 = ld4(sFt + (k+1)*FPITCH + r0);
            float4 a2 = ld4(sFt + (k+2)*FPITCH + r0);
            float4 a3 = ld4(sFt + (k+3)*FPITCH + r0);
            float4 p0 = ld4(sP + (k+0)*DD + c0);
            acc0=fma4(a0.x,p0,acc0); acc1=fma4(a0.y,p0,acc1); acc2=fma4(a0.z,p0,acc2); acc3=fma4(a0.w,p0,acc3);
            float4 p1 = ld4(sP + (k+1)*DD + c0);
            acc0=fma4(a1.x,p1,acc0); acc1=fma4(a1.y,p1,acc1); acc2=fma4(a1.z,p1,acc2); acc3=fma4(a1.w,p1,acc3);
            float4 p2 = ld4(sP + (k+2)*DD + c0);
            acc0=fma4(a2.x,p2,acc0); acc1=fma4(a2.y,p2,acc1); acc2=fma4(a2.z,p2,acc2); acc3=fma4(a2.w,p2,acc3);
            float4 p3 = ld4(sP + (k+3)*DD + c0);
            acc0=fma4(a3.x,p3,acc0); acc1=fma4(a3.y,p3,acc1); acc2=fma4(a3.z,p3,acc2); acc3=fma4(a3.w,p3,acc3);
        }
        st4(sT + (r0+0)*DD + c0, acc0);
        st4(sT + (r0+1)*DD + c0, acc1);
        st4(sT + (r0+2)*DD + c0, acc2);
        st4(sT + (r0+3)*DD + c0, acc3);
    }
    __syncthreads();

    // GEMM2: pred_cov = T @ F^T + Q
    {
        const int r0 = ty*4, c0 = tx*4;
        float4 acc0=make_float4(0,0,0,0), acc1=acc0, acc2=acc0, acc3=acc0;
        for (int k=0;k<DD;k+=4){
            float4 t0 = ld4(sT + (r0+0)*DD + k);
            float4 t1 = ld4(sT + (r0+1)*DD + k);
            float4 t2 = ld4(sT + (r0+2)*DD + k);
            float4 t3 = ld4(sT + (r0+3)*DD + k);
            float4 f0 = ld4(sFt + (k+0)*FPITCH + c0);
            acc0=fma4(t0.x,f0,acc0); acc1=fma4(t1.x,f0,acc1); acc2=fma4(t2.x,f0,acc2); acc3=fma4(t3.x,f0,acc3);
            float4 f1 = ld4(sFt + (k+1)*FPITCH + c0);
            acc0=fma4(t0.y,f1,acc0); acc1=fma4(t1.y,f1,acc1); acc2=fma4(t2.y,f1,acc2); acc3=fma4(t3.y,f1,acc3);
            float4 f2 = ld4(sFt + (k+2)*FPITCH + c0);
            acc0=fma4(t0.z,f2,acc0); acc1=fma4(t1.z,f2,acc1); acc2=fma4(t2.z,f2,acc2); acc3=fma4(t3.z,f2,acc3);
            float4 f3 = ld4(sFt + (k+3)*FPITCH + c0);
            acc0=fma4(t0.w,f3,acc0); acc1=fma4(t1.w,f3,acc1); acc2=fma4(t2.w,f3,acc2); acc3=fma4(t3.w,f3,acc3);
        }
        float pa[4][3], pb[4][3];
        #pragma unroll
        for (int i=0;i<4;i++)
            #pragma unroll
            for (int r=0;r<3;r++){
                pa[i][r] = g_pnf[(r0+i)*3 + r];
                pb[i][r] = g_pnf[(c0+i)*3 + r];
            }
        float* accp[4] = { &acc0.x, &acc1.x, &acc2.x, &acc3.x };
        #pragma unroll
        for (int i=0;i<4;i++){
            #pragma unroll
            for (int j=0;j<4;j++){
                float q = pa[i][0]*pb[j][0];
                q = fmaf(pa[i][1], pb[j][1], q);
                q = fmaf(pa[i][2], pb[j][2], q);
                accp[i][j] += q;
            }
        }
        if (r0 == c0){
            #pragma unroll
            for (int i=0;i<4;i++) accp[i][i] += expf(g_pnd[r0+i]);
        }
        float* cg = scr_cov + (size_t)b*4096;
        st4(sP + (r0+0)*DD + c0, acc0);  st4(cg + (r0+0)*DD + c0, acc0);
        st4(sP + (r0+1)*DD + c0, acc1);  st4(cg + (r0+1)*DD + c0, acc1);
        st4(sP + (r0+2)*DD + c0, acc2);  st4(cg + (r0+2)*DD + c0, acc2);
        st4(sP + (r0+3)*DD + c0, acc3);  st4(cg + (r0+3)*DD + c0, acc3);
    }
    __syncthreads();

    // HP = Hw @ pred_cov
    {
        const int o0 = ty*2, c0 = tx*4;
        float4 accA = make_float4(0,0,0,0), accB = accA;
        const float* hw0 = g_Hw + (o0+0)*DD;
        const float* hw1 = g_Hw + (o0+1)*DD;
        for (int k=0;k<DD;k+=4){
            float4 h0 = ld4(hw0 + k);
            float4 h1 = ld4(hw1 + k);
            float4 p0 = ld4(sP + (k+0)*DD + c0);
            accA=fma4(h0.x,p0,accA); accB=fma4(h1.x,p0,accB);
            float4 p1 = ld4(sP + (k+1)*DD + c0);
            accA=fma4(h0.y,p1,accA); accB=fma4(h1.y,p1,accB);
            float4 p2 = ld4(sP + (k+2)*DD + c0);
            accA=fma4(h0.z,p2,accA); accB=fma4(h1.z,p2,accB);
            float4 p3 = ld4(sP + (k+3)*DD + c0);
            accA=fma4(h0.w,p3,accA); accB=fma4(h1.w,p3,accB);
        }
        float* hg = scr_hp + (size_t)b*2176;
        st4(sHP + (o0+0)*UPITCH + c0, accA);  st4(hg + (o0+0)*UPITCH + c0, accA);
        st4(sHP + (o0+1)*UPITCH + c0, accB);  st4(hg + (o0+1)*UPITCH + c0, accB);
    }
    __syncthreads();

    // S = HP @ Hw^T + Rn
    {
        const int o0 = ty*2, p0 = tx*2;
        float a00=0.f,a01=0.f,a10=0.f,a11=0.f;
        const float* hw0 = g_Hw + (p0+0)*DD;
        const float* hw1 = g_Hw + (p0+1)*DD;
        for (int k=0;k<DD;k+=4){
            float4 x0 = ld4(sHP + (o0+0)*UPITCH + k);
            float4 x1 = ld4(sHP + (o0+1)*UPITCH + k);
            float4 y0 = ld4(hw0 + k);
            float4 y1 = ld4(hw1 + k);
            a00 = dot4acc(x0,y0,a00); a01 = dot4acc(x0,y1,a01);
            a10 = dot4acc(x1,y0,a10); a11 = dot4acc(x1,y1,a11);
        }
        float oa[2][3], ob[2][3];
        #pragma unroll
        for (int i=0;i<2;i++)
            #pragma unroll
            for (int r=0;r<3;r++){
                oa[i][r] = g_onf[(o0+i)*3 + r];
                ob[i][r] = g_onf[(p0+i)*3 + r];
            }
        a00 += oa[0][0]*ob[0][0] + oa[0][1]*ob[0][1] + oa[0][2]*ob[0][2];
        a01 += oa[0][0]*ob[1][0] + oa[0][1]*ob[1][1] + oa[0][2]*ob[1][2];
        a10 += oa[1][0]*ob[0][0] + oa[1][1]*ob[0][1] + oa[1][2]*ob[0][2];
        a11 += oa[1][0]*ob[1][0] + oa[1][1]*ob[1][1] + oa[1][2]*ob[1][2];
        if (o0 == p0){
            a00 += expf(g_ond[o0+0]);
            a11 += expf(g_ond[o0+1]);
        }
        float* sg = scr_s + (size_t)b*1024;
        sg[(o0+0)*OO + p0+0] = a00;
        sg[(o0+0)*OO + p0+1] = a01;
        sg[(o0+1)*OO + p0+0] = a10;
        sg[(o0+1)*OO + p0+1] = a11;
    }
}

// ========== K2: update — warp-specialized loads, 10 CTAs/SM ==========
#define K2_OFF_S   0
#define K2_OFF_RCP (K2_OFF_S   + OO*SPITCH)
#define K2_OFF_U   (K2_OFF_RCP + 32)
#define K2_OFF_PM  (K2_OFF_U   + OO*UPITCH)
#define K2_OFF_RED (K2_OFF_PM  + DD)
#define K2_FLOATS  (K2_OFF_RED + 4)

__global__ __launch_bounds__(128, 10)
void rkn_update(const float* __restrict__ g_obs,
                const float* __restrict__ g_Hw,
                const float* __restrict__ g_Hb,
                float* __restrict__ o_mean,
                float* __restrict__ o_cov,
                float* __restrict__ o_ll)
{
    extern __shared__ float smem[];
    float* sS   = smem + K2_OFF_S;
    float* sRcp = smem + K2_OFF_RCP;
    float* sU   = smem + K2_OFF_U;
    float* spm  = smem + K2_OFF_PM;
    float* sred = smem + K2_OFF_RED;

    const int b   = blockIdx.x;
    const int tid = threadIdx.x;

    if (tid < 32) {
        // ---- warp 0: load S itself, then Cholesky immediately (no CTA barrier) ----
        const int i = tid;
        const float* sg = scr_s + (size_t)b*1024;
        #pragma unroll
        for (int q=0;q<8;q++) st4(sS + i*SPITCH + q*4, ld4(sg + i*OO + q*4));
        __syncwarp();

        for (int j=0;j<32;j++){
            float s = 0.f;
            if (i >= j){
                s = sS[i*SPITCH + j];
                for (int k=0;k<j;k++) s = fmaf(-sS[i*SPITCH+k], sS[j*SPITCH+k], s);
            }
            float dj  = __shfl_sync(0xffffffffu, s, j);
            float ljj = sqrtf(dj);
            if (i == j)      sS[i*SPITCH+j] = ljj;
            else if (i > j)  sS[i*SPITCH+j] = s / ljj;
            __syncwarp();
        }
        float di = sS[i*SPITCH+i];
        sRcp[i] = 1.0f / di;
        float ld = logf(di);
        #pragma unroll
        for (int off=16;off;off>>=1) ld += __shfl_xor_sync(0xffffffffu, ld, off);
        if (i == 0) sred[0] = 2.f*ld;
    } else if (tid < 96) {
        // ---- warps 1-2: load U cols 0..63 + pred_mean ----
        const int t = tid - 32;   // 0..63
        const float* hg = scr_hp + (size_t)b*2176;
        #pragma unroll
        for (int q=0;q<8;q++){
            int f = t*8 + q;          // float4 index, 512 total
            int r = f >> 4, c4 = (f & 15)*4;
            st4(sU + r*UPITCH + c4, ld4(hg + r*UPITCH + c4));
        }
        spm[t] = scr_pm[(size_t)b*DD + t];
    } else {
        // ---- warp 3: innovation -> U col 64 (pred_mean via global, no smem dep) ----
        const int o = tid - 96;
        float acc = g_Hb[o];
        const float* hwr = g_Hw + o*DD;
        const float* pmg = scr_pm + (size_t)b*DD;
        #pragma unroll 8
        for (int k=0;k<DD;k++) acc = fmaf(hwr[k], pmg[k], acc);
        sU[o*UPITCH + 64] = g_obs[b*OO + o] - acc;
    }
    __syncthreads();

    // ---- forward solve L*[U|v] in place: columns thread-private ----
    if (tid < 65) {
        const int c = tid;
        for (int r=0;r<OO;r++){
            float val = sU[r*UPITCH + c];
            for (int k=0;k<r;k++) val = fmaf(-sS[r*SPITCH+k], sU[k*UPITCH + c], val);
            sU[r*UPITCH + c] = val * sRcp[r];
        }
    }
    __syncthreads();

    // ---- outputs ----
    if (tid == 64) {
        float quad = 0.f;
        #pragma unroll
        for (int o=0;o<OO;o++){ float v = sU[o*UPITCH + 64]; quad = fmaf(v, v, quad); }
        o_ll[b] = -0.5f*(sred[0] + quad + 32.f*LOG2PI);
    }
    if (tid < DD) {   // post_mean = pm + U^T v
        float acc = spm[tid];
        #pragma unroll 8
        for (int o=0;o<OO;o++) acc = fmaf(sU[o*UPITCH + tid], sU[o*UPITCH + 64], acc);
        o_mean[(size_t)b*DD + tid] = acc;
    }

    // ---- post_cov = pred_cov - U^T U : two 4x4 passes (low reg pressure) ----
    {
        const int tx = tid & 15, ty = tid >> 4;   // ty 0..7
        const float* cg = scr_cov + (size_t)b*4096;
        float* outr = o_cov + (size_t)b*4096;
        #pragma unroll
        for (int pass=0; pass<2; pass++){
            const int r0 = pass*32 + ty*4, c0 = tx*4;
            float4 acc0=make_float4(0,0,0,0), acc1=acc0, acc2=acc0, acc3=acc0;
            #pragma unroll 4
            for (int o=0;o<OO;o++){
                float4 bv = ld4(sU + o*UPITCH + c0);
                float4 a  = ld4(sU + o*UPITCH + r0);
                acc0 = fma4(a.x, bv, acc0);
                acc1 = fma4(a.y, bv, acc1);
                acc2 = fma4(a.z, bv, acc2);
                acc3 = fma4(a.w, bv, acc3);
            }
            float4 accs[4] = {acc0, acc1, acc2, acc3};
            #pragma unroll
            for (int i=0;i<4;i++){
                float4 pc = ld4(cg + (r0+i)*DD + c0);
                st4(outr + (r0+i)*DD + c0,
                    make_float4(pc.x - accs[i].x, pc.y - accs[i].y,
                                pc.z - accs[i].z, pc.w - accs[i].w));
            }
        }
    }
}

extern "C" void kernel_launch(void* const* d_in, const int* in_sizes, int n_in,
                              void* d_out, int out_size)
{
    const float* g_mean  = (const float*)d_in[0];
    const float* g_cov   = (const float*)d_in[1];
    const float* g_obs   = (const float*)d_in[2];
    const float* g_w1    = (const float*)d_in[3];
    const float* g_b1    = (const float*)d_in[4];
    const float* g_w2    = (const float*)d_in[5];
    const float* g_b2    = (const float*)d_in[6];
    const float* g_basis = (const float*)d_in[7];
    const float* g_pnf   = (const float*)d_in[8];
    const float* g_pnd   = (const float*)d_in[9];
    const float* g_onf   = (const float*)d_in[10];
    const float* g_ond   = (const float*)d_in[11];
    const float* g_Hw    = (const float*)d_in[12];
    const float* g_Hb    = (const float*)d_in[13];

    int B = in_sizes[0] / DD;
    if (B > BMAX) B = BMAX;
    float* out    = (float*)d_out;
    float* o_mean = out;
    float* o_cov  = out + (size_t)B*DD;
    float* o_ll   = out + (size_t)B*DD + (size_t)B*DD*DD;

    const int k1_smem = K1_FLOATS * (int)sizeof(float);
    const int k2_smem = K2_FLOATS * (int)sizeof(float);
    cudaFuncSetAttribute(rkn_predict, cudaFuncAttributeMaxDynamicSharedMemorySize, k1_smem);
    cudaFuncSetAttribute(rkn_update,  cudaFuncAttributeMaxDynamicSharedMemorySize, k2_smem);

    rkn_weights<<<B/8, 256>>>(g_mean, g_w1, g_b1, g_w2, g_b2);
    rkn_mixf<<<dim3(B/16, 4), 256>>>(g_basis);
    rkn_predict<<<B, 256, k1_smem>>>(g_mean, g_cov, g_pnf, g_pnd, g_onf, g_ond, g_Hw);
    rkn_update <<<B, 128, k2_smem>>>(g_obs, g_Hw, g_Hb, o_mean, o_cov, o_ll);
}